// round 2
// baseline (speedup 1.0000x reference)
#include <cuda_runtime.h>
#include <cfloat>

// Problem constants (fixed shapes from reference)
#define BB 4
#define HH 8
#define BHN 32            // BB*HH
#define NN 2048
#define DD 64
#define BM 128            // query rows per block
#define BN 64             // key cols per tile
#define NTILES (NN/BN)    // 32
#define THREADS 256
#define SMEM_BYTES ((BM*16 + BN*16 + BN*16 + BM*16)*16 + BN*4)

// Per-key bias: -|k_j|^2 if mask true else -FLT_MAX.  (-|q_i|^2 is row-constant
// and cancels in softmax; 2*scale folded into Q as 0.25.)
__device__ float g_bias[BHN*NN];
// 1 if mask is stored as int32 words (0/1), 0 if stored as 1-byte bool.
__device__ int g_mask_wide;

// Detect mask storage width. Reads only the first BB*NN bytes, which is safe
// under both layouts. If every byte at offset %4!=0 is zero, storage is int32.
__global__ void detect_kernel(const unsigned char* __restrict__ m) {
    __shared__ int s_or;
    if (threadIdx.x == 0) s_or = 0;
    __syncthreads();
    int acc = 0;
    for (int i = threadIdx.x; i < BB*NN; i += blockDim.x)
        if (i & 3) acc |= m[i];
    if (acc) atomicOr(&s_or, 1);
    __syncthreads();
    if (threadIdx.x == 0) g_mask_wide = (s_or == 0);
}

__global__ void bias_kernel(const float* __restrict__ k,
                            const unsigned char* __restrict__ mask) {
    int idx = blockIdx.x * blockDim.x + threadIdx.x;
    if (idx >= BHN * NN) return;
    int bh = idx >> 11;          // / NN
    int j  = idx & (NN - 1);
    int b  = bh >> 3;            // / HH
    const float4* kr = reinterpret_cast<const float4*>(k) + (size_t)idx * (DD/4);
    float s = 0.f;
#pragma unroll
    for (int t = 0; t < DD/4; t++) {
        float4 f = kr[t];
        s += f.x*f.x + f.y*f.y + f.z*f.z + f.w*f.w;
    }
    bool mv;
    if (g_mask_wide)
        mv = reinterpret_cast<const int*>(mask)[b*NN + j] != 0;
    else
        mv = mask[b*NN + j] != 0;
    g_bias[idx] = mv ? -s : -FLT_MAX;
}

__global__ __launch_bounds__(THREADS, 2)
void attn_kernel(const float* __restrict__ q, const float* __restrict__ k,
                 const float* __restrict__ v, float* __restrict__ out) {
    extern __shared__ float smem[];
    float4* sQ = (float4*)smem;         // BM x 16 float4  (natural, row=query)
    float4* sK = sQ + BM*16;            // BN x 16 float4  (XOR-swizzled)
    float4* sV = sK + BN*16;            // BN x 16 float4  (natural, row=key)
    float4* sP = sV + BN*16;            // BM x 16 float4  (natural)
    float*  sBias = (float*)(sP + BM*16);

    const int tid = threadIdx.x;
    const int tr  = tid >> 4;           // 0..15 -> 8 query rows each
    const int tc  = tid & 15;           // 0..15 -> 4 cols each
    const int bh  = blockIdx.y;
    const int i0  = blockIdx.x * BM;

    const float4* qg = (const float4*)q + (size_t)(bh*NN + i0) * 16;
    const float4* kg = (const float4*)k + (size_t)bh * NN * 16;
    const float4* vg = (const float4*)v + (size_t)bh * NN * 16;
    const float*  biasg = g_bias + bh * NN;

    // Load Q tile once, folding 2*scale = 0.25 into Q.
#pragma unroll
    for (int it = 0; it < BM*16/THREADS; it++) {
        int e = tid + it*THREADS;
        float4 f = qg[e];
        f.x *= 0.25f; f.y *= 0.25f; f.z *= 0.25f; f.w *= 0.25f;
        sQ[e] = f;
    }

    float4 oacc[8];
    float  m_i[8], l_i[8];
#pragma unroll
    for (int i = 0; i < 8; i++) {
        oacc[i] = make_float4(0.f, 0.f, 0.f, 0.f);
        m_i[i] = -FLT_MAX;
        l_i[i] = 0.f;
    }

    for (int t = 0; t < NTILES; t++) {
        __syncthreads();   // previous PV done reading sP/sV
        const float4* kt = kg + t*BN*16;
        const float4* vt = vg + t*BN*16;
#pragma unroll
        for (int it = 0; it < BN*16/THREADS; it++) {
            int e  = tid + it*THREADS;
            int c  = e >> 4, kb = e & 15;
            sK[(c<<4) + (kb ^ ((c>>2)&15))] = kt[e];   // swizzle: conflict-free frag loads
            sV[e] = vt[e];
        }
        if (tid < BN) sBias[tid] = biasg[t*BN + tid];
        __syncthreads();

        // ---- S = (0.25*Q) @ K^T  (8x4 per thread) ----
        float4 sacc[8];
#pragma unroll
        for (int i = 0; i < 8; i++) sacc[i] = make_float4(0.f, 0.f, 0.f, 0.f);
        for (int kb = 0; kb < 16; kb++) {
            int sw = kb ^ tc;
            float4 bk0 = sK[((tc*4+0)<<4) + sw];
            float4 bk1 = sK[((tc*4+1)<<4) + sw];
            float4 bk2 = sK[((tc*4+2)<<4) + sw];
            float4 bk3 = sK[((tc*4+3)<<4) + sw];
#pragma unroll
            for (int i = 0; i < 8; i++) {
                float4 a = sQ[((tr*8+i)<<4) + kb];
                sacc[i].x += a.x*bk0.x + a.y*bk0.y + a.z*bk0.z + a.w*bk0.w;
                sacc[i].y += a.x*bk1.x + a.y*bk1.y + a.z*bk1.z + a.w*bk1.w;
                sacc[i].z += a.x*bk2.x + a.y*bk2.y + a.z*bk2.z + a.w*bk2.w;
                sacc[i].w += a.x*bk3.x + a.y*bk3.y + a.z*bk3.z + a.w*bk3.w;
            }
        }

        // ---- online softmax (row stats reduced over 16 lanes sharing tr) ----
        float b0 = sBias[tc*4+0], b1 = sBias[tc*4+1];
        float b2 = sBias[tc*4+2], b3 = sBias[tc*4+3];
#pragma unroll
        for (int i = 0; i < 8; i++) {
            float sx = sacc[i].x + b0, sy = sacc[i].y + b1;
            float sz = sacc[i].z + b2, sw = sacc[i].w + b3;
            float mt = fmaxf(fmaxf(sx, sy), fmaxf(sz, sw));
#pragma unroll
            for (int off = 1; off < 16; off <<= 1)
                mt = fmaxf(mt, __shfl_xor_sync(0xffffffffu, mt, off));
            float mnew  = fmaxf(m_i[i], mt);
            float alpha = __expf(m_i[i] - mnew);
            float px = __expf(sx - mnew), py = __expf(sy - mnew);
            float pz = __expf(sz - mnew), pw = __expf(sw - mnew);
            float rs = px + py + pz + pw;
#pragma unroll
            for (int off = 1; off < 16; off <<= 1)
                rs += __shfl_xor_sync(0xffffffffu, rs, off);
            m_i[i] = mnew;
            l_i[i] = l_i[i]*alpha + rs;
            oacc[i].x *= alpha; oacc[i].y *= alpha;
            oacc[i].z *= alpha; oacc[i].w *= alpha;
            sP[((tr*8+i)<<4) + tc] = make_float4(px, py, pz, pw);
        }
        __syncthreads();

        // ---- O += P @ V ----
        for (int cb = 0; cb < 16; cb++) {
            float4 bv0 = sV[((cb*4+0)<<4) + tc];
            float4 bv1 = sV[((cb*4+1)<<4) + tc];
            float4 bv2 = sV[((cb*4+2)<<4) + tc];
            float4 bv3 = sV[((cb*4+3)<<4) + tc];
#pragma unroll
            for (int i = 0; i < 8; i++) {
                float4 a = sP[((tr*8+i)<<4) + cb];
                oacc[i].x += a.x*bv0.x + a.y*bv1.x + a.z*bv2.x + a.w*bv3.x;
                oacc[i].y += a.x*bv0.y + a.y*bv1.y + a.z*bv2.y + a.w*bv3.y;
                oacc[i].z += a.x*bv0.z + a.y*bv1.z + a.z*bv2.z + a.w*bv3.z;
                oacc[i].w += a.x*bv0.w + a.y*bv1.w + a.z*bv2.w + a.w*bv3.w;
            }
        }
    }

    // ---- epilogue: divide by l, store ----
    float4* og = (float4*)out + (size_t)(bh*NN + i0) * 16;
#pragma unroll
    for (int i = 0; i < 8; i++) {
        float inv = 1.f / l_i[i];
        float4 o = oacc[i];
        o.x *= inv; o.y *= inv; o.z *= inv; o.w *= inv;
        og[((tr*8+i)<<4) + tc] = o;
    }
}

extern "C" void kernel_launch(void* const* d_in, const int* in_sizes, int n_in,
                              void* d_out, int out_size) {
    // Locate mask input by element count (BB*NN = 8192); q/k/v keep dict order.
    int mask_idx = 3;
    for (int i = 0; i < n_in; i++)
        if (in_sizes[i] == BB*NN) { mask_idx = i; break; }
    const float* fin[3];
    int fi = 0;
    for (int i = 0; i < n_in && fi < 3; i++)
        if (i != mask_idx) fin[fi++] = (const float*)d_in[i];

    const float* q = fin[0];
    const float* k = fin[1];
    const float* v = fin[2];
    const unsigned char* mask = (const unsigned char*)d_in[mask_idx];
    float* out = (float*)d_out;

    cudaFuncSetAttribute(attn_kernel,
                         cudaFuncAttributeMaxDynamicSharedMemorySize, SMEM_BYTES);

    detect_kernel<<<1, 256>>>(mask);
    bias_kernel<<<(BHN*NN + 255)/256, 256>>>(k, mask);
    attn_kernel<<<dim3(NN/BM, BHN), THREADS, SMEM_BYTES>>>(q, k, v, out);
}

// round 3
// speedup vs baseline: 1.5832x; 1.5832x over previous
#include <cuda_runtime.h>
#include <cfloat>

#define BB 4
#define HH 8
#define BHN 32            // BB*HH
#define NN 2048
#define DD 64
#define BM 128            // query rows per block
#define BN 64             // key cols per tile
#define NTILES (NN/BN)    // 32
#define THREADS 256

#define SQ_PITCH 68
#define SK_PITCH 68
#define SV_PITCH 72
#define LOG2E 1.44269504088896f

#define SQ_SIZE (BM*SQ_PITCH)
#define SK_SIZE (BN*SK_PITCH)
#define SV_SIZE (BN*SV_PITCH)
#define SMEM_BYTES ((SQ_SIZE + SK_SIZE + SV_SIZE + BN)*4)

// Per-key bias in log2 domain: -log2e*|k_j|^2 if mask true, else -FLT_MAX.
// (-|q_i|^2 is row-constant -> cancels in softmax; 2*scale folded into Q.)
__device__ float g_bias[BHN*NN];
__device__ int g_mask_wide;   // 1 if mask stored as int32 words, 0 if 1-byte bool

__global__ void detect_kernel(const unsigned char* __restrict__ m) {
    __shared__ int s_or;
    if (threadIdx.x == 0) s_or = 0;
    __syncthreads();
    int acc = 0;
    for (int i = threadIdx.x; i < BB*NN; i += blockDim.x)
        if (i & 3) acc |= m[i];
    if (acc) atomicOr(&s_or, 1);
    __syncthreads();
    if (threadIdx.x == 0) g_mask_wide = (s_or == 0);
}

__global__ void bias_kernel(const float* __restrict__ k,
                            const unsigned char* __restrict__ mask) {
    int idx = blockIdx.x * blockDim.x + threadIdx.x;
    if (idx >= BHN * NN) return;
    int bh = idx >> 11;
    int j  = idx & (NN - 1);
    int b  = bh >> 3;
    const float4* kr = reinterpret_cast<const float4*>(k) + (size_t)idx * (DD/4);
    float s = 0.f;
#pragma unroll
    for (int t = 0; t < DD/4; t++) {
        float4 f = kr[t];
        s += f.x*f.x + f.y*f.y + f.z*f.z + f.w*f.w;
    }
    bool mv;
    if (g_mask_wide)
        mv = reinterpret_cast<const int*>(mask)[b*NN + j] != 0;
    else
        mv = mask[b*NN + j] != 0;
    g_bias[idx] = mv ? (-s * LOG2E) : -FLT_MAX;   // masked NOT scaled (avoid -inf)
}

__device__ __forceinline__ unsigned f2tf(float x) {
    unsigned r; asm("cvt.rna.tf32.f32 %0, %1;" : "=r"(r) : "f"(x)); return r;
}
__device__ __forceinline__ float ex2(float x) {
    float r; asm("ex2.approx.f32 %0, %1;" : "=f"(r) : "f"(x)); return r;
}
__device__ __forceinline__ void mma_tf32(float* d, const unsigned* a,
                                         unsigned b0, unsigned b1) {
    asm volatile(
        "mma.sync.aligned.m16n8k8.row.col.f32.tf32.tf32.f32 "
        "{%0,%1,%2,%3}, {%4,%5,%6,%7}, {%8,%9}, {%0,%1,%2,%3};"
        : "+f"(d[0]), "+f"(d[1]), "+f"(d[2]), "+f"(d[3])
        : "r"(a[0]), "r"(a[1]), "r"(a[2]), "r"(a[3]), "r"(b0), "r"(b1));
}

__global__ __launch_bounds__(THREADS, 2)
void attn_kernel(const float* __restrict__ q, const float* __restrict__ k,
                 const float* __restrict__ v, float* __restrict__ out) {
    extern __shared__ float smem[];
    float* sQ = smem;                 // [128][68] fp32, Q pre-scaled
    float* sK = sQ + SQ_SIZE;         // [64][68] fp32
    float* sV = sK + SK_SIZE;         // [64][72] fp32
    float* sBias = sV + SV_SIZE;      // [64]

    const int tid  = threadIdx.x;
    const int w    = tid >> 5;        // warp id: rows 16w..16w+15
    const int lane = tid & 31;
    const int g    = lane >> 2;       // group id (row within frag)
    const int m    = lane & 3;        // thread-in-group (k / col index)
    const int bh   = blockIdx.y;
    const int i0   = blockIdx.x * BM;

    const float4* qg = (const float4*)(q + (size_t)(bh*NN + i0)*DD);
    const float4* kg = (const float4*)(k + (size_t)bh*NN*DD);
    const float4* vg = (const float4*)(v + (size_t)bh*NN*DD);
    const float*  biasg = g_bias + bh*NN;

    // Load Q once, pre-scaled by 0.25*log2e (2*scale, log2 domain)
    const float qs = 0.25f * LOG2E;
#pragma unroll
    for (int it = 0; it < BM*DD/4/THREADS; it++) {   // 8 iters
        int e = tid + it*THREADS;
        int r = e >> 4, c4 = e & 15;
        float4 f = qg[e];
        float* dst = sQ + r*SQ_PITCH + c4*4;
        dst[0] = f.x*qs; dst[1] = f.y*qs; dst[2] = f.z*qs; dst[3] = f.w*qs;
    }

    float oacc[8][4];
#pragma unroll
    for (int nt = 0; nt < 8; nt++)
#pragma unroll
        for (int i = 0; i < 4; i++) oacc[nt][i] = 0.f;
    float m_lo = -FLT_MAX, m_hi = -FLT_MAX, l_lo = 0.f, l_hi = 0.f;

    for (int t = 0; t < NTILES; t++) {
        __syncthreads();   // prior PV done reading sV
#pragma unroll
        for (int it = 0; it < BN*DD/4/THREADS; it++) {   // 4 iters
            int e = tid + it*THREADS;
            int r = e >> 4, c4 = e & 15;
            float4 fk = kg[t*BN*(DD/4) + e];
            float4 fv = vg[t*BN*(DD/4) + e];
            float* dk = sK + r*SK_PITCH + c4*4;
            dk[0]=fk.x; dk[1]=fk.y; dk[2]=fk.z; dk[3]=fk.w;
            float* dv = sV + r*SV_PITCH + c4*4;
            dv[0]=fv.x; dv[1]=fv.y; dv[2]=fv.z; dv[3]=fv.w;
        }
        if (tid < BN) sBias[tid] = biasg[t*BN + tid];
        __syncthreads();

        // ---- S = Q @ K^T via tf32x3 (hi*hi + hi*lo + lo*hi) ----
        float sacc[8][4];
#pragma unroll
        for (int nt = 0; nt < 8; nt++)
#pragma unroll
            for (int i = 0; i < 4; i++) sacc[nt][i] = 0.f;

        const float* qbase = sQ + (w*16 + g)*SQ_PITCH + m;
        const float* kbase = sK + g*SK_PITCH + m;
#pragma unroll
        for (int c = 0; c < 8; c++) {
            float a0f = qbase[c*8];
            float a1f = qbase[8*SQ_PITCH + c*8];
            float a2f = qbase[c*8 + 4];
            float a3f = qbase[8*SQ_PITCH + c*8 + 4];
            unsigned ah[4], al[4];
            ah[0]=f2tf(a0f); ah[1]=f2tf(a1f); ah[2]=f2tf(a2f); ah[3]=f2tf(a3f);
            al[0]=f2tf(a0f - __uint_as_float(ah[0]));
            al[1]=f2tf(a1f - __uint_as_float(ah[1]));
            al[2]=f2tf(a2f - __uint_as_float(ah[2]));
            al[3]=f2tf(a3f - __uint_as_float(ah[3]));
            const float* kb = kbase + c*8;
#pragma unroll
            for (int nt = 0; nt < 8; nt++) {
                float b0f = kb[nt*8*SK_PITCH];
                float b1f = kb[nt*8*SK_PITCH + 4];
                unsigned bh0 = f2tf(b0f), bh1 = f2tf(b1f);
                unsigned bl0 = f2tf(b0f - __uint_as_float(bh0));
                unsigned bl1 = f2tf(b1f - __uint_as_float(bh1));
                mma_tf32(sacc[nt], ah, bh0, bh1);
                mma_tf32(sacc[nt], ah, bl0, bl1);
                mma_tf32(sacc[nt], al, bh0, bh1);
            }
        }

        // ---- online softmax on C fragments (log2 domain) ----
        float vlo = -FLT_MAX, vhi = -FLT_MAX;
#pragma unroll
        for (int nt = 0; nt < 8; nt++) {
            float b0 = sBias[nt*8 + 2*m];
            float b1 = sBias[nt*8 + 2*m + 1];
            sacc[nt][0] += b0; sacc[nt][1] += b1;
            sacc[nt][2] += b0; sacc[nt][3] += b1;
            vlo = fmaxf(vlo, fmaxf(sacc[nt][0], sacc[nt][1]));
            vhi = fmaxf(vhi, fmaxf(sacc[nt][2], sacc[nt][3]));
        }
        vlo = fmaxf(vlo, __shfl_xor_sync(0xffffffffu, vlo, 1));
        vlo = fmaxf(vlo, __shfl_xor_sync(0xffffffffu, vlo, 2));
        vhi = fmaxf(vhi, __shfl_xor_sync(0xffffffffu, vhi, 1));
        vhi = fmaxf(vhi, __shfl_xor_sync(0xffffffffu, vhi, 2));
        float mn_lo = fmaxf(m_lo, vlo), mn_hi = fmaxf(m_hi, vhi);
        float al_lo = ex2(m_lo - mn_lo), al_hi = ex2(m_hi - mn_hi);
        m_lo = mn_lo; m_hi = mn_hi;

        float rs_lo = 0.f, rs_hi = 0.f;
#pragma unroll
        for (int nt = 0; nt < 8; nt++) {
            float p0 = ex2(sacc[nt][0] - mn_lo);
            float p1 = ex2(sacc[nt][1] - mn_lo);
            float p2 = ex2(sacc[nt][2] - mn_hi);
            float p3 = ex2(sacc[nt][3] - mn_hi);
            // round to tf32 now; use the SAME rounded values for l and for PV
            unsigned u0 = f2tf(p0), u1 = f2tf(p1), u2 = f2tf(p2), u3 = f2tf(p3);
            rs_lo += __uint_as_float(u0) + __uint_as_float(u1);
            rs_hi += __uint_as_float(u2) + __uint_as_float(u3);
            sacc[nt][0] = __uint_as_float(u0);
            sacc[nt][1] = __uint_as_float(u1);
            sacc[nt][2] = __uint_as_float(u2);
            sacc[nt][3] = __uint_as_float(u3);
            oacc[nt][0] *= al_lo; oacc[nt][1] *= al_lo;
            oacc[nt][2] *= al_hi; oacc[nt][3] *= al_hi;
        }
        rs_lo += __shfl_xor_sync(0xffffffffu, rs_lo, 1);
        rs_lo += __shfl_xor_sync(0xffffffffu, rs_lo, 2);
        rs_hi += __shfl_xor_sync(0xffffffffu, rs_hi, 1);
        rs_hi += __shfl_xor_sync(0xffffffffu, rs_hi, 2);
        l_lo = l_lo*al_lo + rs_lo;
        l_hi = l_hi*al_hi + rs_hi;

        // ---- O += P @ (V_hi + V_lo): C-frag -> A-frag via quad shuffles ----
        const int qsrc = (lane & ~3) | (m >> 1);
#pragma unroll
        for (int c = 0; c < 8; c++) {
            float p0 = sacc[c][0], p1 = sacc[c][1];
            float p2 = sacc[c][2], p3 = sacc[c][3];
            float t0 = __shfl_sync(0xffffffffu, p0, qsrc);
            float t1 = __shfl_sync(0xffffffffu, p1, qsrc);
            float u0 = __shfl_sync(0xffffffffu, p0, qsrc + 2);
            float u1 = __shfl_sync(0xffffffffu, p1, qsrc + 2);
            float t2 = __shfl_sync(0xffffffffu, p2, qsrc);
            float t3 = __shfl_sync(0xffffffffu, p3, qsrc);
            float u2 = __shfl_sync(0xffffffffu, p2, qsrc + 2);
            float u3 = __shfl_sync(0xffffffffu, p3, qsrc + 2);
            unsigned a[4];
            a[0] = __float_as_uint((m & 1) ? t1 : t0);  // (row g,   k=m)
            a[1] = __float_as_uint((m & 1) ? t3 : t2);  // (row g+8, k=m)
            a[2] = __float_as_uint((m & 1) ? u1 : u0);  // (row g,   k=m+4)
            a[3] = __float_as_uint((m & 1) ? u3 : u2);  // (row g+8, k=m+4)
            const float* vb = sV + (c*8 + m)*SV_PITCH + g;
#pragma unroll
            for (int nt = 0; nt < 8; nt++) {
                float b0f = vb[nt*8];
                float b1f = vb[4*SV_PITCH + nt*8];
                unsigned bh0 = f2tf(b0f), bh1 = f2tf(b1f);
                unsigned bl0 = f2tf(b0f - __uint_as_float(bh0));
                unsigned bl1 = f2tf(b1f - __uint_as_float(bh1));
                mma_tf32(oacc[nt], a, bh0, bh1);
                mma_tf32(oacc[nt], a, bl0, bl1);
            }
        }
    }

    // ---- epilogue ----
    float il_lo = 1.f / l_lo, il_hi = 1.f / l_hi;
    float* og = out + (size_t)(bh*NN + i0 + w*16)*DD;
#pragma unroll
    for (int nt = 0; nt < 8; nt++) {
        float2 lo2 = make_float2(oacc[nt][0]*il_lo, oacc[nt][1]*il_lo);
        float2 hi2 = make_float2(oacc[nt][2]*il_hi, oacc[nt][3]*il_hi);
        *(float2*)(og + g*DD + nt*8 + 2*m) = lo2;
        *(float2*)(og + (g+8)*DD + nt*8 + 2*m) = hi2;
    }
}

extern "C" void kernel_launch(void* const* d_in, const int* in_sizes, int n_in,
                              void* d_out, int out_size) {
    // Locate mask input by element count (BB*NN = 8192); q/k/v keep dict order.
    int mask_idx = 3;
    for (int i = 0; i < n_in; i++)
        if (in_sizes[i] == BB*NN) { mask_idx = i; break; }
    const float* fin[3];
    int fi = 0;
    for (int i = 0; i < n_in && fi < 3; i++)
        if (i != mask_idx) fin[fi++] = (const float*)d_in[i];

    const float* q = fin[0];
    const float* k = fin[1];
    const float* v = fin[2];
    const unsigned char* mask = (const unsigned char*)d_in[mask_idx];
    float* out = (float*)d_out;

    cudaFuncSetAttribute(attn_kernel,
                         cudaFuncAttributeMaxDynamicSharedMemorySize, SMEM_BYTES);

    detect_kernel<<<1, 256>>>(mask);
    bias_kernel<<<(BHN*NN + 255)/256, 256>>>(k, mask);
    attn_kernel<<<dim3(NN/BM, BHN), THREADS, SMEM_BYTES>>>(q, k, v, out);
}

// round 4
// speedup vs baseline: 2.0182x; 1.2748x over previous
#include <cuda_runtime.h>
#include <cfloat>

#define BB 4
#define HH 8
#define BHN 32            // BB*HH
#define NN 2048
#define DD 64
#define BM 128            // query rows per block
#define BN 64             // key cols per tile
#define NTILES (NN/BN)    // 32
#define THREADS 256

#define SQ_PITCH 68
#define SK_PITCH 68
#define SV_PITCH 72
#define LOG2E 1.44269504088896f

#define SQ_SIZE (BM*SQ_PITCH)
#define SK_SIZE (BN*SK_PITCH)
#define SV_SIZE (BN*SV_PITCH)
// sQ + sKh + sKl + sVh + sVl + bias
#define SMEM_BYTES ((SQ_SIZE + 2*SK_SIZE + 2*SV_SIZE + BN)*4)

// Per-key bias in log2 domain: -log2e*|k_j|^2 if mask true, else -FLT_MAX.
// (-|q_i|^2 is row-constant -> cancels in softmax; 2*scale folded into Q.)
__device__ float g_bias[BHN*NN];

// Merged detect+bias: each block redundantly detects mask storage width
// (int32 words vs 1-byte bool) by checking bytes at offset %4 != 0 over the
// whole 8KB mask (L2-resident). Keeps the graph at 2 launches per replay so
// ncu -s 5 lands on attn_kernel.
__global__ void bias_kernel(const float* __restrict__ k,
                            const unsigned char* __restrict__ mask) {
    const unsigned* mw = (const unsigned*)mask;
    int acc = 0;
    for (int i = threadIdx.x; i < BB*NN/4; i += blockDim.x)
        acc |= (mw[i] & 0xFFFFFF00u);
    int any = __syncthreads_or(acc);
    bool wide = (any == 0);

    int idx = blockIdx.x * blockDim.x + threadIdx.x;
    if (idx >= BHN * NN) return;
    int bh = idx >> 11;
    int j  = idx & (NN - 1);
    int b  = bh >> 3;
    const float4* kr = reinterpret_cast<const float4*>(k) + (size_t)idx * (DD/4);
    float s = 0.f;
#pragma unroll
    for (int t = 0; t < DD/4; t++) {
        float4 f = kr[t];
        s += f.x*f.x + f.y*f.y + f.z*f.z + f.w*f.w;
    }
    bool mv;
    if (wide)
        mv = reinterpret_cast<const int*>(mask)[b*NN + j] != 0;
    else
        mv = mask[b*NN + j] != 0;
    g_bias[idx] = mv ? (-s * LOG2E) : -FLT_MAX;   // masked NOT scaled (avoid -inf)
}

__device__ __forceinline__ unsigned f2tf(float x) {
    unsigned r; asm("cvt.rna.tf32.f32 %0, %1;" : "=r"(r) : "f"(x)); return r;
}
__device__ __forceinline__ float f2tf_f(float x) {
    return __uint_as_float(f2tf(x));
}
__device__ __forceinline__ float ex2(float x) {
    float r; asm("ex2.approx.f32 %0, %1;" : "=f"(r) : "f"(x)); return r;
}
__device__ __forceinline__ void mma_tf32(float* d, const unsigned* a,
                                         unsigned b0, unsigned b1) {
    asm volatile(
        "mma.sync.aligned.m16n8k8.row.col.f32.tf32.tf32.f32 "
        "{%0,%1,%2,%3}, {%4,%5,%6,%7}, {%8,%9}, {%0,%1,%2,%3};"
        : "+f"(d[0]), "+f"(d[1]), "+f"(d[2]), "+f"(d[3])
        : "r"(a[0]), "r"(a[1]), "r"(a[2]), "r"(a[3]), "r"(b0), "r"(b1));
}

__global__ __launch_bounds__(THREADS, 2)
void attn_kernel(const float* __restrict__ q, const float* __restrict__ k,
                 const float* __restrict__ v, float* __restrict__ out) {
    extern __shared__ float smem[];
    float* sQ  = smem;                 // [128][68] fp32, Q pre-scaled
    float* sKh = sQ  + SQ_SIZE;        // [64][68] tf32 hi
    float* sKl = sKh + SK_SIZE;        // [64][68] tf32 lo
    float* sVh = sKl + SK_SIZE;        // [64][72] tf32 hi
    float* sVl = sVh + SV_SIZE;        // [64][72] tf32 lo
    float* sBias = sVl + SV_SIZE;      // [64]

    const int tid  = threadIdx.x;
    const int w    = tid >> 5;        // warp id: rows 16w..16w+15
    const int lane = tid & 31;
    const int g    = lane >> 2;       // group id (row within frag)
    const int m    = lane & 3;        // thread-in-group (k / col index)
    const int bh   = blockIdx.y;
    const int i0   = blockIdx.x * BM;

    const float4* qg = (const float4*)(q + (size_t)(bh*NN + i0)*DD);
    const float4* kg = (const float4*)(k + (size_t)bh*NN*DD);
    const float4* vg = (const float4*)(v + (size_t)bh*NN*DD);
    const float*  biasg = g_bias + bh*NN;

    // Load Q once, pre-scaled by 0.25*log2e (2*scale, log2 domain)
    const float qs = 0.25f * LOG2E;
#pragma unroll
    for (int it = 0; it < BM*DD/4/THREADS; it++) {   // 8 iters
        int e = tid + it*THREADS;
        int r = e >> 4, c4 = e & 15;
        float4 f = qg[e];
        float* dst = sQ + r*SQ_PITCH + c4*4;
        dst[0] = f.x*qs; dst[1] = f.y*qs; dst[2] = f.z*qs; dst[3] = f.w*qs;
    }

    float oacc[8][4];
#pragma unroll
    for (int nt = 0; nt < 8; nt++)
#pragma unroll
        for (int i = 0; i < 4; i++) oacc[nt][i] = 0.f;
    float m_lo = -FLT_MAX, m_hi = -FLT_MAX, l_lo = 0.f, l_hi = 0.f;

    for (int t = 0; t < NTILES; t++) {
        __syncthreads();   // prior PV done reading sV
#pragma unroll
        for (int it = 0; it < BN*DD/4/THREADS; it++) {   // 4 iters
            int e = tid + it*THREADS;
            int r = e >> 4, c4 = e & 15;
            float4 fk = kg[t*BN*(DD/4) + e];
            float4 fv = vg[t*BN*(DD/4) + e];
            // split once here instead of 8x in the consumers
            float4 kh, kl, vh, vl;
            kh.x = f2tf_f(fk.x); kl.x = f2tf_f(fk.x - kh.x);
            kh.y = f2tf_f(fk.y); kl.y = f2tf_f(fk.y - kh.y);
            kh.z = f2tf_f(fk.z); kl.z = f2tf_f(fk.z - kh.z);
            kh.w = f2tf_f(fk.w); kl.w = f2tf_f(fk.w - kh.w);
            vh.x = f2tf_f(fv.x); vl.x = f2tf_f(fv.x - vh.x);
            vh.y = f2tf_f(fv.y); vl.y = f2tf_f(fv.y - vh.y);
            vh.z = f2tf_f(fv.z); vl.z = f2tf_f(fv.z - vh.z);
            vh.w = f2tf_f(fv.w); vl.w = f2tf_f(fv.w - vh.w);
            float* dkh = sKh + r*SK_PITCH + c4*4;
            float* dkl = sKl + r*SK_PITCH + c4*4;
            dkh[0]=kh.x; dkh[1]=kh.y; dkh[2]=kh.z; dkh[3]=kh.w;
            dkl[0]=kl.x; dkl[1]=kl.y; dkl[2]=kl.z; dkl[3]=kl.w;
            float* dvh = sVh + r*SV_PITCH + c4*4;
            float* dvl = sVl + r*SV_PITCH + c4*4;
            dvh[0]=vh.x; dvh[1]=vh.y; dvh[2]=vh.z; dvh[3]=vh.w;
            dvl[0]=vl.x; dvl[1]=vl.y; dvl[2]=vl.z; dvl[3]=vl.w;
        }
        if (tid < BN) sBias[tid] = biasg[t*BN + tid];
        __syncthreads();

        // ---- S = Q @ K^T via tf32x3 (hi*hi + hi*lo + lo*hi) ----
        float sacc[8][4];
#pragma unroll
        for (int nt = 0; nt < 8; nt++)
#pragma unroll
            for (int i = 0; i < 4; i++) sacc[nt][i] = 0.f;

        const float* qbase = sQ  + (w*16 + g)*SQ_PITCH + m;
        const float* khb   = sKh + g*SK_PITCH + m;
        const float* klb   = sKl + g*SK_PITCH + m;
#pragma unroll
        for (int c = 0; c < 8; c++) {
            float a0f = qbase[c*8];
            float a1f = qbase[8*SQ_PITCH + c*8];
            float a2f = qbase[c*8 + 4];
            float a3f = qbase[8*SQ_PITCH + c*8 + 4];
            unsigned ah[4], al[4];
            ah[0]=f2tf(a0f); ah[1]=f2tf(a1f); ah[2]=f2tf(a2f); ah[3]=f2tf(a3f);
            al[0]=f2tf(a0f - __uint_as_float(ah[0]));
            al[1]=f2tf(a1f - __uint_as_float(ah[1]));
            al[2]=f2tf(a2f - __uint_as_float(ah[2]));
            al[3]=f2tf(a3f - __uint_as_float(ah[3]));
#pragma unroll
            for (int nt = 0; nt < 8; nt++) {
                unsigned bh0 = __float_as_uint(khb[nt*8*SK_PITCH + c*8]);
                unsigned bh1 = __float_as_uint(khb[nt*8*SK_PITCH + c*8 + 4]);
                unsigned bl0 = __float_as_uint(klb[nt*8*SK_PITCH + c*8]);
                unsigned bl1 = __float_as_uint(klb[nt*8*SK_PITCH + c*8 + 4]);
                mma_tf32(sacc[nt], ah, bh0, bh1);
                mma_tf32(sacc[nt], ah, bl0, bl1);
                mma_tf32(sacc[nt], al, bh0, bh1);
            }
        }

        // ---- online softmax on C fragments (log2 domain) ----
        float vlo = -FLT_MAX, vhi = -FLT_MAX;
#pragma unroll
        for (int nt = 0; nt < 8; nt++) {
            float b0 = sBias[nt*8 + 2*m];
            float b1 = sBias[nt*8 + 2*m + 1];
            sacc[nt][0] += b0; sacc[nt][1] += b1;
            sacc[nt][2] += b0; sacc[nt][3] += b1;
            vlo = fmaxf(vlo, fmaxf(sacc[nt][0], sacc[nt][1]));
            vhi = fmaxf(vhi, fmaxf(sacc[nt][2], sacc[nt][3]));
        }
        vlo = fmaxf(vlo, __shfl_xor_sync(0xffffffffu, vlo, 1));
        vlo = fmaxf(vlo, __shfl_xor_sync(0xffffffffu, vlo, 2));
        vhi = fmaxf(vhi, __shfl_xor_sync(0xffffffffu, vhi, 1));
        vhi = fmaxf(vhi, __shfl_xor_sync(0xffffffffu, vhi, 2));
        float mn_lo = fmaxf(m_lo, vlo), mn_hi = fmaxf(m_hi, vhi);
        float al_lo = ex2(m_lo - mn_lo), al_hi = ex2(m_hi - mn_hi);
        m_lo = mn_lo; m_hi = mn_hi;

        float rs_lo = 0.f, rs_hi = 0.f;
#pragma unroll
        for (int nt = 0; nt < 8; nt++) {
            float p0 = ex2(sacc[nt][0] - mn_lo);
            float p1 = ex2(sacc[nt][1] - mn_lo);
            float p2 = ex2(sacc[nt][2] - mn_hi);
            float p3 = ex2(sacc[nt][3] - mn_hi);
            // round to tf32 now; use the SAME rounded values for l and for PV
            unsigned u0 = f2tf(p0), u1 = f2tf(p1), u2 = f2tf(p2), u3 = f2tf(p3);
            rs_lo += __uint_as_float(u0) + __uint_as_float(u1);
            rs_hi += __uint_as_float(u2) + __uint_as_float(u3);
            sacc[nt][0] = __uint_as_float(u0);
            sacc[nt][1] = __uint_as_float(u1);
            sacc[nt][2] = __uint_as_float(u2);
            sacc[nt][3] = __uint_as_float(u3);
            oacc[nt][0] *= al_lo; oacc[nt][1] *= al_lo;
            oacc[nt][2] *= al_hi; oacc[nt][3] *= al_hi;
        }
        rs_lo += __shfl_xor_sync(0xffffffffu, rs_lo, 1);
        rs_lo += __shfl_xor_sync(0xffffffffu, rs_lo, 2);
        rs_hi += __shfl_xor_sync(0xffffffffu, rs_hi, 1);
        rs_hi += __shfl_xor_sync(0xffffffffu, rs_hi, 2);
        l_lo = l_lo*al_lo + rs_lo;
        l_hi = l_hi*al_hi + rs_hi;

        // ---- O += P @ (V_hi + V_lo): C-frag -> A-frag via quad shuffles ----
        const int qsrc = (lane & ~3) | (m >> 1);
#pragma unroll
        for (int c = 0; c < 8; c++) {
            float p0 = sacc[c][0], p1 = sacc[c][1];
            float p2 = sacc[c][2], p3 = sacc[c][3];
            float t0 = __shfl_sync(0xffffffffu, p0, qsrc);
            float t1 = __shfl_sync(0xffffffffu, p1, qsrc);
            float u0 = __shfl_sync(0xffffffffu, p0, qsrc + 2);
            float u1 = __shfl_sync(0xffffffffu, p1, qsrc + 2);
            float t2 = __shfl_sync(0xffffffffu, p2, qsrc);
            float t3 = __shfl_sync(0xffffffffu, p3, qsrc);
            float u2 = __shfl_sync(0xffffffffu, p2, qsrc + 2);
            float u3 = __shfl_sync(0xffffffffu, p3, qsrc + 2);
            unsigned a[4];
            a[0] = __float_as_uint((m & 1) ? t1 : t0);  // (row g,   k=m)
            a[1] = __float_as_uint((m & 1) ? t3 : t2);  // (row g+8, k=m)
            a[2] = __float_as_uint((m & 1) ? u1 : u0);  // (row g,   k=m+4)
            a[3] = __float_as_uint((m & 1) ? u3 : u2);  // (row g+8, k=m+4)
            const float* vhb = sVh + (c*8 + m)*SV_PITCH + g;
            const float* vlb = sVl + (c*8 + m)*SV_PITCH + g;
#pragma unroll
            for (int nt = 0; nt < 8; nt++) {
                unsigned bh0 = __float_as_uint(vhb[nt*8]);
                unsigned bh1 = __float_as_uint(vhb[4*SV_PITCH + nt*8]);
                unsigned bl0 = __float_as_uint(vlb[nt*8]);
                unsigned bl1 = __float_as_uint(vlb[4*SV_PITCH + nt*8]);
                mma_tf32(oacc[nt], a, bh0, bh1);
                mma_tf32(oacc[nt], a, bl0, bl1);
            }
        }
    }

    // ---- epilogue ----
    float il_lo = 1.f / l_lo, il_hi = 1.f / l_hi;
    float* og = out + (size_t)(bh*NN + i0 + w*16)*DD;
#pragma unroll
    for (int nt = 0; nt < 8; nt++) {
        float2 lo2 = make_float2(oacc[nt][0]*il_lo, oacc[nt][1]*il_lo);
        float2 hi2 = make_float2(oacc[nt][2]*il_hi, oacc[nt][3]*il_hi);
        *(float2*)(og + g*DD + nt*8 + 2*m) = lo2;
        *(float2*)(og + (g+8)*DD + nt*8 + 2*m) = hi2;
    }
}

extern "C" void kernel_launch(void* const* d_in, const int* in_sizes, int n_in,
                              void* d_out, int out_size) {
    // Locate mask input by element count (BB*NN = 8192); q/k/v keep dict order.
    int mask_idx = 3;
    for (int i = 0; i < n_in; i++)
        if (in_sizes[i] == BB*NN) { mask_idx = i; break; }
    const float* fin[3];
    int fi = 0;
    for (int i = 0; i < n_in && fi < 3; i++)
        if (i != mask_idx) fin[fi++] = (const float*)d_in[i];

    const float* q = fin[0];
    const float* k = fin[1];
    const float* v = fin[2];
    const unsigned char* mask = (const unsigned char*)d_in[mask_idx];
    float* out = (float*)d_out;

    cudaFuncSetAttribute(attn_kernel,
                         cudaFuncAttributeMaxDynamicSharedMemorySize, SMEM_BYTES);

    bias_kernel<<<(BHN*NN + 255)/256, 256>>>(k, mask);
    attn_kernel<<<dim3(NN/BM, BHN), THREADS, SMEM_BYTES>>>(q, k, v, out);
}

// round 6
// speedup vs baseline: 2.0321x; 1.0069x over previous
#include <cuda_runtime.h>
#include <cfloat>

#define BB 4
#define HH 8
#define BHN 32            // BB*HH
#define NN 2048
#define DD 64
#define BM 128            // query rows per block
#define BN 64             // key cols per tile
#define NTILES (NN/BN)    // 32
#define THREADS 256

#define SQ_PITCH 68
#define SK_PITCH 68
#define SV_PITCH 72
#define LOG2E 1.44269504088896f

#define SQ_SIZE (BM*SQ_PITCH)
#define SK_SIZE (BN*SK_PITCH)
#define SV_SIZE (BN*SV_PITCH)
// sQ + sKh + sKl + sVh + sVl + bias
#define SMEM_BYTES ((SQ_SIZE + 2*SK_SIZE + 2*SV_SIZE + BN)*4)

// Per-key bias in log2 domain: -log2e*|k_j|^2 if mask true, else -FLT_MAX.
// (-|q_i|^2 is row-constant -> cancels in softmax; 2*scale folded into Q.)
__device__ float g_bias[BHN*NN];

// Merged detect+bias: each block redundantly detects mask storage width
// (int32 words vs 1-byte bool) by checking bytes at offset %4 != 0 over the
// whole 8KB mask (L2-resident). Keeps the graph at 2 launches per replay so
// ncu -s 5 lands on attn_kernel.
__global__ void bias_kernel(const float* __restrict__ k,
                            const unsigned char* __restrict__ mask) {
    const unsigned* mw = (const unsigned*)mask;
    int acc = 0;
    for (int i = threadIdx.x; i < BB*NN/4; i += blockDim.x)
        acc |= (mw[i] & 0xFFFFFF00u);
    int any = __syncthreads_or(acc);
    bool wide = (any == 0);

    int idx = blockIdx.x * blockDim.x + threadIdx.x;
    if (idx >= BHN * NN) return;
    int bh = idx >> 11;
    int j  = idx & (NN - 1);
    int b  = bh >> 3;
    const float4* kr = reinterpret_cast<const float4*>(k) + (size_t)idx * (DD/4);
    float s = 0.f;
#pragma unroll
    for (int t = 0; t < DD/4; t++) {
        float4 f = kr[t];
        s += f.x*f.x + f.y*f.y + f.z*f.z + f.w*f.w;
    }
    bool mv;
    if (wide)
        mv = reinterpret_cast<const int*>(mask)[b*NN + j] != 0;
    else
        mv = mask[b*NN + j] != 0;
    g_bias[idx] = mv ? (-s * LOG2E) : -FLT_MAX;   // masked NOT scaled (avoid -inf)
}

__device__ __forceinline__ unsigned f2tf(float x) {
    unsigned r; asm("cvt.rna.tf32.f32 %0, %1;" : "=r"(r) : "f"(x)); return r;
}
__device__ __forceinline__ float f2tf_f(float x) {
    return __uint_as_float(f2tf(x));
}
__device__ __forceinline__ float ex2(float x) {
    float r; asm("ex2.approx.f32 %0, %1;" : "=f"(r) : "f"(x)); return r;
}
__device__ __forceinline__ void mma_tf32(float* d, const unsigned* a,
                                         unsigned b0, unsigned b1) {
    asm volatile(
        "mma.sync.aligned.m16n8k8.row.col.f32.tf32.tf32.f32 "
        "{%0,%1,%2,%3}, {%4,%5,%6,%7}, {%8,%9}, {%0,%1,%2,%3};"
        : "+f"(d[0]), "+f"(d[1]), "+f"(d[2]), "+f"(d[3])
        : "r"(a[0]), "r"(a[1]), "r"(a[2]), "r"(a[3]), "r"(b0), "r"(b1));
}

__global__ __launch_bounds__(THREADS, 2)
void attn_kernel(const float* __restrict__ q, const float* __restrict__ k,
                 const float* __restrict__ v, float* __restrict__ out) {
    extern __shared__ float smem[];
    float* sQ  = smem;                 // [128][68] fp32, Q pre-scaled
    float* sKh = sQ  + SQ_SIZE;        // [64][68] tf32 hi
    float* sKl = sKh + SK_SIZE;        // [64][68] tf32 lo
    float* sVh = sKl + SK_SIZE;        // [64][72] tf32 hi
    float* sVl = sVh + SV_SIZE;        // [64][72] tf32 lo
    float* sBias = sVl + SV_SIZE;      // [64]

    const int tid  = threadIdx.x;
    const int w    = tid >> 5;        // warp id: rows 16w..16w+15
    const int lane = tid & 31;
    const int g    = lane >> 2;       // group id (row within frag)
    const int m    = lane & 3;        // thread-in-group (k / col index)
    const int bh   = blockIdx.y;
    const int i0   = blockIdx.x * BM;

    const float4* qg = (const float4*)(q + (size_t)(bh*NN + i0)*DD);
    const float4* kg = (const float4*)(k + (size_t)bh*NN*DD);
    const float4* vg = (const float4*)(v + (size_t)bh*NN*DD);
    const float*  biasg = g_bias + bh*NN;

    // Load Q once, pre-scaled by 0.25*log2e (2*scale, log2 domain)
    const float qs = 0.25f * LOG2E;
#pragma unroll
    for (int it = 0; it < BM*DD/4/THREADS; it++) {   // 8 iters
        int e = tid + it*THREADS;
        int r = e >> 4, c4 = e & 15;
        float4 f = qg[e];
        float* dst = sQ + r*SQ_PITCH + c4*4;
        dst[0] = f.x*qs; dst[1] = f.y*qs; dst[2] = f.z*qs; dst[3] = f.w*qs;
    }

    float oacc[8][4];
#pragma unroll
    for (int nt = 0; nt < 8; nt++)
#pragma unroll
        for (int i = 0; i < 4; i++) oacc[nt][i] = 0.f;
    float m_lo = -FLT_MAX, m_hi = -FLT_MAX, l_lo = 0.f, l_hi = 0.f;

    for (int t = 0; t < NTILES; t++) {
        __syncthreads();   // prior PV done reading sV
#pragma unroll
        for (int it = 0; it < BN*DD/4/THREADS; it++) {   // 4 iters
            int e = tid + it*THREADS;
            int r = e >> 4, c4 = e & 15;
            float4 fk = kg[t*BN*(DD/4) + e];
            float4 fv = vg[t*BN*(DD/4) + e];
            // split once here instead of 8x in the consumers
            float4 kh, kl, vh, vl;
            kh.x = f2tf_f(fk.x); kl.x = f2tf_f(fk.x - kh.x);
            kh.y = f2tf_f(fk.y); kl.y = f2tf_f(fk.y - kh.y);
            kh.z = f2tf_f(fk.z); kl.z = f2tf_f(fk.z - kh.z);
            kh.w = f2tf_f(fk.w); kl.w = f2tf_f(fk.w - kh.w);
            vh.x = f2tf_f(fv.x); vl.x = f2tf_f(fv.x - vh.x);
            vh.y = f2tf_f(fv.y); vl.y = f2tf_f(fv.y - vh.y);
            vh.z = f2tf_f(fv.z); vl.z = f2tf_f(fv.z - vh.z);
            vh.w = f2tf_f(fv.w); vl.w = f2tf_f(fv.w - vh.w);
            float* dkh = sKh + r*SK_PITCH + c4*4;
            float* dkl = sKl + r*SK_PITCH + c4*4;
            dkh[0]=kh.x; dkh[1]=kh.y; dkh[2]=kh.z; dkh[3]=kh.w;
            dkl[0]=kl.x; dkl[1]=kl.y; dkl[2]=kl.z; dkl[3]=kl.w;
            float* dvh = sVh + r*SV_PITCH + c4*4;
            float* dvl = sVl + r*SV_PITCH + c4*4;
            dvh[0]=vh.x; dvh[1]=vh.y; dvh[2]=vh.z; dvh[3]=vh.w;
            dvl[0]=vl.x; dvl[1]=vl.y; dvl[2]=vl.z; dvl[3]=vl.w;
        }
        if (tid < BN) sBias[tid] = biasg[t*BN + tid];
        __syncthreads();

        // ---- S = Q @ K^T via tf32x3 (hi*hi + hi*lo + lo*hi) ----
        float sacc[8][4];
#pragma unroll
        for (int nt = 0; nt < 8; nt++)
#pragma unroll
            for (int i = 0; i < 4; i++) sacc[nt][i] = 0.f;

        const float* qbase = sQ  + (w*16 + g)*SQ_PITCH + m;
        const float* khb   = sKh + g*SK_PITCH + m;
        const float* klb   = sKl + g*SK_PITCH + m;
#pragma unroll
        for (int c = 0; c < 8; c++) {
            float a0f = qbase[c*8];
            float a1f = qbase[8*SQ_PITCH + c*8];
            float a2f = qbase[c*8 + 4];
            float a3f = qbase[8*SQ_PITCH + c*8 + 4];
            unsigned ah[4], al[4];
            ah[0]=f2tf(a0f); ah[1]=f2tf(a1f); ah[2]=f2tf(a2f); ah[3]=f2tf(a3f);
            al[0]=f2tf(a0f - __uint_as_float(ah[0]));
            al[1]=f2tf(a1f - __uint_as_float(ah[1]));
            al[2]=f2tf(a2f - __uint_as_float(ah[2]));
            al[3]=f2tf(a3f - __uint_as_float(ah[3]));
#pragma unroll
            for (int nt = 0; nt < 8; nt++) {
                unsigned bh0 = __float_as_uint(khb[nt*8*SK_PITCH + c*8]);
                unsigned bh1 = __float_as_uint(khb[nt*8*SK_PITCH + c*8 + 4]);
                unsigned bl0 = __float_as_uint(klb[nt*8*SK_PITCH + c*8]);
                unsigned bl1 = __float_as_uint(klb[nt*8*SK_PITCH + c*8 + 4]);
                mma_tf32(sacc[nt], ah, bh0, bh1);
                mma_tf32(sacc[nt], ah, bl0, bl1);
                mma_tf32(sacc[nt], al, bh0, bh1);
            }
        }

        // ---- online softmax on C fragments (log2 domain) ----
        float vlo = -FLT_MAX, vhi = -FLT_MAX;
#pragma unroll
        for (int nt = 0; nt < 8; nt++) {
            float b0 = sBias[nt*8 + 2*m];
            float b1 = sBias[nt*8 + 2*m + 1];
            sacc[nt][0] += b0; sacc[nt][1] += b1;
            sacc[nt][2] += b0; sacc[nt][3] += b1;
            vlo = fmaxf(vlo, fmaxf(sacc[nt][0], sacc[nt][1]));
            vhi = fmaxf(vhi, fmaxf(sacc[nt][2], sacc[nt][3]));
        }
        vlo = fmaxf(vlo, __shfl_xor_sync(0xffffffffu, vlo, 1));
        vlo = fmaxf(vlo, __shfl_xor_sync(0xffffffffu, vlo, 2));
        vhi = fmaxf(vhi, __shfl_xor_sync(0xffffffffu, vhi, 1));
        vhi = fmaxf(vhi, __shfl_xor_sync(0xffffffffu, vhi, 2));
        float mn_lo = fmaxf(m_lo, vlo), mn_hi = fmaxf(m_hi, vhi);
        float al_lo = ex2(m_lo - mn_lo), al_hi = ex2(m_hi - mn_hi);
        m_lo = mn_lo; m_hi = mn_hi;

        float rs_lo = 0.f, rs_hi = 0.f;
#pragma unroll
        for (int nt = 0; nt < 8; nt++) {
            float p0 = ex2(sacc[nt][0] - mn_lo);
            float p1 = ex2(sacc[nt][1] - mn_lo);
            float p2 = ex2(sacc[nt][2] - mn_hi);
            float p3 = ex2(sacc[nt][3] - mn_hi);
            // round to tf32 now; use the SAME rounded values for l and for PV
            unsigned u0 = f2tf(p0), u1 = f2tf(p1), u2 = f2tf(p2), u3 = f2tf(p3);
            rs_lo += __uint_as_float(u0) + __uint_as_float(u1);
            rs_hi += __uint_as_float(u2) + __uint_as_float(u3);
            sacc[nt][0] = __uint_as_float(u0);
            sacc[nt][1] = __uint_as_float(u1);
            sacc[nt][2] = __uint_as_float(u2);
            sacc[nt][3] = __uint_as_float(u3);
            oacc[nt][0] *= al_lo; oacc[nt][1] *= al_lo;
            oacc[nt][2] *= al_hi; oacc[nt][3] *= al_hi;
        }
        rs_lo += __shfl_xor_sync(0xffffffffu, rs_lo, 1);
        rs_lo += __shfl_xor_sync(0xffffffffu, rs_lo, 2);
        rs_hi += __shfl_xor_sync(0xffffffffu, rs_hi, 1);
        rs_hi += __shfl_xor_sync(0xffffffffu, rs_hi, 2);
        l_lo = l_lo*al_lo + rs_lo;
        l_hi = l_hi*al_hi + rs_hi;

        // ---- O += P @ (V_hi + V_lo): C-frag -> A-frag via quad shuffles ----
        const int qsrc = (lane & ~3) | (m >> 1);
#pragma unroll
        for (int c = 0; c < 8; c++) {
            float p0 = sacc[c][0], p1 = sacc[c][1];
            float p2 = sacc[c][2], p3 = sacc[c][3];
            float t0 = __shfl_sync(0xffffffffu, p0, qsrc);
            float t1 = __shfl_sync(0xffffffffu, p1, qsrc);
            float u0 = __shfl_sync(0xffffffffu, p0, qsrc + 2);
            float u1 = __shfl_sync(0xffffffffu, p1, qsrc + 2);
            float t2 = __shfl_sync(0xffffffffu, p2, qsrc);
            float t3 = __shfl_sync(0xffffffffu, p3, qsrc);
            float u2 = __shfl_sync(0xffffffffu, p2, qsrc + 2);
            float u3 = __shfl_sync(0xffffffffu, p3, qsrc + 2);
            unsigned a[4];
            a[0] = __float_as_uint((m & 1) ? t1 : t0);  // (row g,   k=m)
            a[1] = __float_as_uint((m & 1) ? t3 : t2);  // (row g+8, k=m)
            a[2] = __float_as_uint((m & 1) ? u1 : u0);  // (row g,   k=m+4)
            a[3] = __float_as_uint((m & 1) ? u3 : u2);  // (row g+8, k=m+4)
            const float* vhb = sVh + (c*8 + m)*SV_PITCH + g;
            const float* vlb = sVl + (c*8 + m)*SV_PITCH + g;
#pragma unroll
            for (int nt = 0; nt < 8; nt++) {
                unsigned bh0 = __float_as_uint(vhb[nt*8]);
                unsigned bh1 = __float_as_uint(vhb[4*SV_PITCH + nt*8]);
                unsigned bl0 = __float_as_uint(vlb[nt*8]);
                unsigned bl1 = __float_as_uint(vlb[4*SV_PITCH + nt*8]);
                mma_tf32(oacc[nt], a, bh0, bh1);
                mma_tf32(oacc[nt], a, bl0, bl1);
            }
        }
    }

    // ---- epilogue ----
    float il_lo = 1.f / l_lo, il_hi = 1.f / l_hi;
    float* og = out + (size_t)(bh*NN + i0 + w*16)*DD;
#pragma unroll
    for (int nt = 0; nt < 8; nt++) {
        float2 lo2 = make_float2(oacc[nt][0]*il_lo, oacc[nt][1]*il_lo);
        float2 hi2 = make_float2(oacc[nt][2]*il_hi, oacc[nt][3]*il_hi);
        *(float2*)(og + g*DD + nt*8 + 2*m) = lo2;
        *(float2*)(og + (g+8)*DD + nt*8 + 2*m) = hi2;
    }
}

extern "C" void kernel_launch(void* const* d_in, const int* in_sizes, int n_in,
                              void* d_out, int out_size) {
    // Locate mask input by element count (BB*NN = 8192); q/k/v keep dict order.
    int mask_idx = 3;
    for (int i = 0; i < n_in; i++)
        if (in_sizes[i] == BB*NN) { mask_idx = i; break; }
    const float* fin[3];
    int fi = 0;
    for (int i = 0; i < n_in && fi < 3; i++)
        if (i != mask_idx) fin[fi++] = (const float*)d_in[i];

    const float* q = fin[0];
    const float* k = fin[1];
    const float* v = fin[2];
    const unsigned char* mask = (const unsigned char*)d_in[mask_idx];
    float* out = (float*)d_out;

    cudaFuncSetAttribute(attn_kernel,
                         cudaFuncAttributeMaxDynamicSharedMemorySize, SMEM_BYTES);

    bias_kernel<<<(BHN*NN + 255)/256, 256>>>(k, mask);
    attn_kernel<<<dim3(NN/BM, BHN), THREADS, SMEM_BYTES>>>(q, k, v, out);
}